// round 16
// baseline (speedup 1.0000x reference)
#include <cuda_runtime.h>
#include <cuda_bf16.h>
#include <cstdint>

// GriddingDistance round 16: round-5 schedule (validated optimum) with a
// single-wave persistent scatter:
//   - 1184 blocks (8/SM on 148 SMs) x 256 thr, grid-stride over points
//     -> one block-wave, no wave-transition tails, launch/retire amortized
//   - software-pipelined point loads (next point's LDGs issue before the
//     current point's REDs) -> LDG latency hides under RED issue
//   L0 cudaMemsetAsync pred half
//   L1 pred scatter (persistent) || gt zero
//   L2 gt scatter (persistent)
// Scatter math = round-5 winner (z-window v2/v4 vector REDs).

#define GRID_R 128
#define GSZ    (GRID_R * GRID_R * GRID_R)
#define SCAT_BLOCKS 1184     // 8 per SM x 148 SMs

__device__ __forceinline__ void red_add_f32(float* p, float v) {
    atomicAdd(p, v);  // return unused -> REDG
}
__device__ __forceinline__ void red_add_v2_f32(float* p, float a, float b) {
    asm volatile("red.global.add.v2.f32 [%0], {%1, %2};"
                 :: "l"(p), "f"(a), "f"(b) : "memory");
}
__device__ __forceinline__ void red_add_v4_f32(float* p, float a, float b,
                                               float c, float d) {
    asm volatile("red.global.add.v4.f32 [%0], {%1, %2, %3, %4};"
                 :: "l"(p), "f"(a), "f"(b), "f"(c), "f"(d) : "memory");
}

__device__ __forceinline__ void scatter_point(float px, float py, float pz,
                                              float* __restrict__ gb)
{
    px = fmaf(px, 128.0f, 64.0f);
    py = fmaf(py, 128.0f, 64.0f);
    pz = fmaf(pz, 128.0f, 64.0f);

    float fx = floorf(px), fy = floorf(py), fz = floorf(pz);
    float dx = px - fx,   dy = py - fy,   dz = pz - fz;
    int ix = (int)fx, iy = (int)fy, iz = (int)fz;

    float wx0 = 1.0f - dx, wy0 = 1.0f - dy, wz0 = 1.0f - dz;
    float w00 = wx0 * wy0, w01 = wx0 * dy, w10 = dx * wy0, w11 = dx * dy;

    bool interior = (ix >= 0) & (ix + 1 < GRID_R) &
                    (iy >= 0) & (iy + 1 < GRID_R) &
                    (iz >= 0) & (iz + 1 < GRID_R);

    if (interior) {
        int r00 = (ix * GRID_R + iy) * GRID_R + iz;
        int r01 = r00 + GRID_R;
        int r10 = r00 + GRID_R * GRID_R;
        int r11 = r10 + GRID_R;

        float a00 = w00 * wz0, b00 = w00 * dz;
        float a01 = w01 * wz0, b01 = w01 * dz;
        float a10 = w10 * wz0, b10 = w10 * dz;
        float a11 = w11 * wz0, b11 = w11 * dz;

        int m4 = iz & 3;
        if ((m4 & 1) == 0) {
            red_add_v2_f32(gb + r00, a00, b00);
            red_add_v2_f32(gb + r01, a01, b01);
            red_add_v2_f32(gb + r10, a10, b10);
            red_add_v2_f32(gb + r11, a11, b11);
        } else if (m4 == 1) {
            red_add_v4_f32(gb + r00 - 1, 0.f, a00, b00, 0.f);
            red_add_v4_f32(gb + r01 - 1, 0.f, a01, b01, 0.f);
            red_add_v4_f32(gb + r10 - 1, 0.f, a10, b10, 0.f);
            red_add_v4_f32(gb + r11 - 1, 0.f, a11, b11, 0.f);
        } else {
            red_add_f32(gb + r00,     a00);
            red_add_f32(gb + r00 + 1, b00);
            red_add_f32(gb + r01,     a01);
            red_add_f32(gb + r01 + 1, b01);
            red_add_f32(gb + r10,     a10);
            red_add_f32(gb + r10 + 1, b10);
            red_add_f32(gb + r11,     a11);
            red_add_f32(gb + r11 + 1, b11);
        }
    } else {
        int ix0 = min(max(ix,     0), GRID_R - 1);
        int ix1 = min(max(ix + 1, 0), GRID_R - 1);
        int iy0 = min(max(iy,     0), GRID_R - 1);
        int iy1 = min(max(iy + 1, 0), GRID_R - 1);
        int iz0 = min(max(iz,     0), GRID_R - 1);
        int iz1 = min(max(iz + 1, 0), GRID_R - 1);
        int rx0 = ix0 * GRID_R * GRID_R, rx1 = ix1 * GRID_R * GRID_R;
        int ry0 = iy0 * GRID_R,          ry1 = iy1 * GRID_R;
        red_add_f32(gb + (rx0 + ry0 + iz0), w00 * wz0);
        red_add_f32(gb + (rx0 + ry0 + iz1), w00 * dz);
        red_add_f32(gb + (rx0 + ry1 + iz0), w01 * wz0);
        red_add_f32(gb + (rx0 + ry1 + iz1), w01 * dz);
        red_add_f32(gb + (rx1 + ry0 + iz0), w10 * wz0);
        red_add_f32(gb + (rx1 + ry0 + iz1), w10 * dz);
        red_add_f32(gb + (rx1 + ry1 + iz0), w11 * wz0);
        red_add_f32(gb + (rx1 + ry1 + iz1), w11 * dz);
    }
}

// Persistent grid-stride scatter with software-pipelined loads.
__device__ __forceinline__ void scatter_persistent(const float* __restrict__ pts,
                                                   float* __restrict__ g,
                                                   int n_per_sample,
                                                   int total_points,
                                                   int nblocks)
{
    int stride = nblocks * blockDim.x;
    int t = blockIdx.x * blockDim.x + threadIdx.x;
    if (t >= total_points) return;

    // prologue: load first point
    float px = pts[3 * t + 0];
    float py = pts[3 * t + 1];
    float pz = pts[3 * t + 2];
    int   s  = t / n_per_sample;

    for (;;) {
        int tn = t + stride;
        bool more = (tn < total_points);

        float nx = 0.f, ny = 0.f, nz = 0.f;
        int   ns = 0;
        if (more) {                        // next point's loads issue BEFORE
            nx = pts[3 * tn + 0];          // the current point's REDs
            ny = pts[3 * tn + 1];
            nz = pts[3 * tn + 2];
            ns = tn / n_per_sample;
        }

        scatter_point(px, py, pz, g + (long long)s * GSZ);

        if (!more) break;
        px = nx; py = ny; pz = nz; s = ns; t = tn;
    }
}

__device__ __forceinline__ void zero_range(float* __restrict__ base,
                                           long long nfloats,
                                           int nblocks)
{
    float4* z = (float4*)base;
    unsigned n4 = (unsigned)(nfloats >> 2);
    unsigned stride = (unsigned)nblocks * blockDim.x;
    float4 zero = make_float4(0.f, 0.f, 0.f, 0.f);
    for (unsigned i = blockIdx.x * blockDim.x + threadIdx.x;
         i < n4; i += stride)
        z[i] = zero;
}

// L1: y==0 persistent pred scatter; y==1 zero gt half.
__global__ __launch_bounds__(256)
void scatter_pred_zero_gt_kernel(const float* __restrict__ pred,
                                 float* __restrict__ out,
                                 int n_per_sample,
                                 int total_points,
                                 long long grid_per_cloud)
{
    if (blockIdx.y == 0) {
        scatter_persistent(pred, out, n_per_sample, total_points, gridDim.x);
    } else {
        zero_range(out + grid_per_cloud, grid_per_cloud, gridDim.x);
    }
}

// L2: persistent gt scatter.
__global__ __launch_bounds__(256)
void scatter_gt_kernel(const float* __restrict__ gt,
                       float* __restrict__ g,
                       int n_per_sample,
                       int total_points)
{
    scatter_persistent(gt, g, n_per_sample, total_points, gridDim.x);
}

extern "C" void kernel_launch(void* const* d_in, const int* in_sizes, int n_in,
                              void* d_out, int out_size)
{
    const float* pred = (const float*)d_in[0];
    const float* gt   = (const float*)d_in[1];
    float* out = (float*)d_out;

    int b = out_size / (2 * GSZ);                      // 8
    int total_points = in_sizes[0] / 3;                // 524288
    int n = total_points / b;                          // 65536
    long long grid_per_cloud = (long long)b * GSZ;     // 16777216 floats

    // L0: zero pred half (fast memset path; L2-resident for L1)
    cudaMemsetAsync(out, 0, (size_t)grid_per_cloud * sizeof(float));

    // L1: persistent pred scatter || gt zero
    scatter_pred_zero_gt_kernel<<<dim3(SCAT_BLOCKS, 2), 256>>>(
        pred, out, n, total_points, grid_per_cloud);

    // L2: persistent gt scatter
    scatter_gt_kernel<<<SCAT_BLOCKS, 256>>>(gt, out + grid_per_cloud,
                                            n, total_points);
}

// round 17
// speedup vs baseline: 1.0465x; 1.0465x over previous
#include <cuda_runtime.h>
#include <cuda_bf16.h>
#include <cstdint>

// GriddingDistance round 17: TMA bulk-store zero for the exposed pred
// zero-fill (targets the path-independent LTS cap ~6300B/cyc; memset path
// measured 6.7TB/s, STG 4.8TB/s) + the round-13-validated PDL chain:
//   K0 zero pred half via cp.async.bulk SMEM->GMEM, early launch_dependents
//   K1 (PSS) pred scatter (loads+math pre-wait, REDs post-wait) || gt zero
//   K2 (PSS) gt scatter (deep prologue)
// Scatter math = round-5 winner (z-window v2/v4 vector REDs).

#define GRID_R 128
#define GSZ    (GRID_R * GRID_R * GRID_R)
#define ZCHUNK 16384            // bytes per bulk store
#define ZBLOCKS 1024

__device__ __forceinline__ void pdl_wait() {
    asm volatile("griddepcontrol.wait;" ::: "memory");
}
__device__ __forceinline__ void pdl_trigger() {
    asm volatile("griddepcontrol.launch_dependents;");
}

__device__ __forceinline__ void red_add_f32(float* p, float v) {
    atomicAdd(p, v);  // return unused -> REDG
}
__device__ __forceinline__ void red_add_v2_f32(float* p, float a, float b) {
    asm volatile("red.global.add.v2.f32 [%0], {%1, %2};"
                 :: "l"(p), "f"(a), "f"(b) : "memory");
}
__device__ __forceinline__ void red_add_v4_f32(float* p, float a, float b,
                                               float c, float d) {
    asm volatile("red.global.add.v4.f32 [%0], {%1, %2, %3, %4};"
                 :: "l"(p), "f"(a), "f"(b), "f"(c), "f"(d) : "memory");
}

template <bool WAIT>
__device__ __forceinline__ void scatter_point(float px, float py, float pz,
                                              float* __restrict__ gb)
{
    px = fmaf(px, 128.0f, 64.0f);
    py = fmaf(py, 128.0f, 64.0f);
    pz = fmaf(pz, 128.0f, 64.0f);

    float fx = floorf(px), fy = floorf(py), fz = floorf(pz);
    float dx = px - fx,   dy = py - fy,   dz = pz - fz;
    int ix = (int)fx, iy = (int)fy, iz = (int)fz;

    float wx0 = 1.0f - dx, wy0 = 1.0f - dy, wz0 = 1.0f - dz;
    float w00 = wx0 * wy0, w01 = wx0 * dy, w10 = dx * wy0, w11 = dx * dy;

    bool interior = (ix >= 0) & (ix + 1 < GRID_R) &
                    (iy >= 0) & (iy + 1 < GRID_R) &
                    (iz >= 0) & (iz + 1 < GRID_R);

    if (interior) {
        int r00 = (ix * GRID_R + iy) * GRID_R + iz;
        int r01 = r00 + GRID_R;
        int r10 = r00 + GRID_R * GRID_R;
        int r11 = r10 + GRID_R;

        float a00 = w00 * wz0, b00 = w00 * dz;
        float a01 = w01 * wz0, b01 = w01 * dz;
        float a10 = w10 * wz0, b10 = w10 * dz;
        float a11 = w11 * wz0, b11 = w11 * dz;

        if (WAIT) pdl_wait();

        int m4 = iz & 3;
        if ((m4 & 1) == 0) {
            red_add_v2_f32(gb + r00, a00, b00);
            red_add_v2_f32(gb + r01, a01, b01);
            red_add_v2_f32(gb + r10, a10, b10);
            red_add_v2_f32(gb + r11, a11, b11);
        } else if (m4 == 1) {
            red_add_v4_f32(gb + r00 - 1, 0.f, a00, b00, 0.f);
            red_add_v4_f32(gb + r01 - 1, 0.f, a01, b01, 0.f);
            red_add_v4_f32(gb + r10 - 1, 0.f, a10, b10, 0.f);
            red_add_v4_f32(gb + r11 - 1, 0.f, a11, b11, 0.f);
        } else {
            red_add_f32(gb + r00,     a00);
            red_add_f32(gb + r00 + 1, b00);
            red_add_f32(gb + r01,     a01);
            red_add_f32(gb + r01 + 1, b01);
            red_add_f32(gb + r10,     a10);
            red_add_f32(gb + r10 + 1, b10);
            red_add_f32(gb + r11,     a11);
            red_add_f32(gb + r11 + 1, b11);
        }
    } else {
        int ix0 = min(max(ix,     0), GRID_R - 1);
        int ix1 = min(max(ix + 1, 0), GRID_R - 1);
        int iy0 = min(max(iy,     0), GRID_R - 1);
        int iy1 = min(max(iy + 1, 0), GRID_R - 1);
        int iz0 = min(max(iz,     0), GRID_R - 1);
        int iz1 = min(max(iz + 1, 0), GRID_R - 1);
        int rx0 = ix0 * GRID_R * GRID_R, rx1 = ix1 * GRID_R * GRID_R;
        int ry0 = iy0 * GRID_R,          ry1 = iy1 * GRID_R;

        if (WAIT) pdl_wait();

        red_add_f32(gb + (rx0 + ry0 + iz0), w00 * wz0);
        red_add_f32(gb + (rx0 + ry0 + iz1), w00 * dz);
        red_add_f32(gb + (rx0 + ry1 + iz0), w01 * wz0);
        red_add_f32(gb + (rx0 + ry1 + iz1), w01 * dz);
        red_add_f32(gb + (rx1 + ry0 + iz0), w10 * wz0);
        red_add_f32(gb + (rx1 + ry0 + iz1), w10 * dz);
        red_add_f32(gb + (rx1 + ry1 + iz0), w11 * wz0);
        red_add_f32(gb + (rx1 + ry1 + iz1), w11 * dz);
    }
}

// K0: zero pred half via TMA bulk stores from a zeroed 16KB SMEM buffer.
__global__ __launch_bounds__(128)
void zero_pred_tma_kernel(char* __restrict__ dst, long long nbytes)
{
    __shared__ __align__(128) char buf[ZCHUNK];

    float4* b4 = (float4*)buf;
    float4 zero = make_float4(0.f, 0.f, 0.f, 0.f);
    #pragma unroll
    for (int i = threadIdx.x; i < ZCHUNK / 16; i += 128)
        b4[i] = zero;
    __syncthreads();

    if (threadIdx.x == 0) {
        asm volatile("fence.proxy.async.shared::cta;" ::: "memory");
        unsigned saddr;
        asm("{ .reg .u64 t; cvta.to.shared.u64 t, %1; cvt.u32.u64 %0, t; }"
            : "=r"(saddr) : "l"(buf));

        long long nchunks = (nbytes + ZCHUNK - 1) / ZCHUNK;
        for (long long c = blockIdx.x; c < nchunks; c += gridDim.x) {
            long long off = c * (long long)ZCHUNK;
            long long rem = nbytes - off;
            unsigned size = (rem >= ZCHUNK) ? ZCHUNK : (unsigned)rem;
            asm volatile(
                "cp.async.bulk.global.shared::cta.bulk_group [%0], [%1], %2;"
                :: "l"(dst + off), "r"(saddr), "r"(size) : "memory");
        }
        asm volatile("cp.async.bulk.commit_group;" ::: "memory");
        asm volatile("cp.async.bulk.wait_group 0;" ::: "memory");
    }
    __syncthreads();
    pdl_trigger();
}

// K1: y==0 pred scatter (deep prologue, wait before REDs); y==1 gt zero.
__global__ __launch_bounds__(256)
void scatter_pred_zero_gt_kernel(const float* __restrict__ pred,
                                 float* __restrict__ out,
                                 int n_per_sample,
                                 int total_points,
                                 long long grid_per_cloud)
{
    if (blockIdx.y == 0) {
        int t = blockIdx.x * blockDim.x + threadIdx.x;
        if (t < total_points) {
            const float* p = pred + 3 * t;
            float px = p[0], py = p[1], pz = p[2];
            int sample = t / n_per_sample;
            scatter_point<true>(px, py, pz, out + (long long)sample * GSZ);
        } else {
            pdl_wait();
        }
    } else {
        // gt-half zero: independent of K0's pred zeros -> no wait
        float4* z = (float4*)(out + grid_per_cloud);
        unsigned n4 = (unsigned)(grid_per_cloud >> 2);
        unsigned stride = gridDim.x * blockDim.x;
        float4 zero = make_float4(0.f, 0.f, 0.f, 0.f);
        for (unsigned i = blockIdx.x * blockDim.x + threadIdx.x;
             i < n4; i += stride)
            z[i] = zero;
    }
    __threadfence();
    pdl_trigger();
}

// K2: gt scatter, deep prologue.
__global__ __launch_bounds__(256)
void scatter_gt_kernel(const float* __restrict__ gt,
                       float* __restrict__ g,
                       int n_per_sample,
                       int total_points)
{
    int t = blockIdx.x * blockDim.x + threadIdx.x;
    if (t < total_points) {
        const float* p = gt + 3 * t;
        float px = p[0], py = p[1], pz = p[2];
        int sample = t / n_per_sample;
        scatter_point<true>(px, py, pz, g + (long long)sample * GSZ);
    } else {
        pdl_wait();
    }
}

extern "C" void kernel_launch(void* const* d_in, const int* in_sizes, int n_in,
                              void* d_out, int out_size)
{
    const float* pred = (const float*)d_in[0];
    const float* gt   = (const float*)d_in[1];
    float* out = (float*)d_out;

    int b = out_size / (2 * GSZ);                      // 8
    int total_points = in_sizes[0] / 3;                // 524288
    int n = total_points / b;                          // 65536
    long long grid_per_cloud = (long long)b * GSZ;     // 16777216 floats

    int nblk = (total_points + 255) / 256;             // 2048

    // K0: TMA bulk-store zero of pred half (early PDL trigger)
    zero_pred_tma_kernel<<<ZBLOCKS, 128>>>((char*)out,
                                           grid_per_cloud * (long long)sizeof(float));

    // K1: pred scatter || gt zero (programmatic dependency on K0)
    {
        cudaLaunchConfig_t cfg = {};
        cudaLaunchAttribute attr[1];
        attr[0].id = cudaLaunchAttributeProgrammaticStreamSerialization;
        attr[0].val.programmaticStreamSerializationAllowed = 1;
        cfg.attrs = attr;
        cfg.numAttrs = 1;
        cfg.gridDim = dim3(nblk, 2, 1);
        cfg.blockDim = dim3(256, 1, 1);
        cfg.stream = 0;
        cudaLaunchKernelEx(&cfg, scatter_pred_zero_gt_kernel,
                           pred, out, n, total_points, grid_per_cloud);
    }

    // K2: gt scatter (programmatic dependency on K1)
    {
        cudaLaunchConfig_t cfg = {};
        cudaLaunchAttribute attr[1];
        attr[0].id = cudaLaunchAttributeProgrammaticStreamSerialization;
        attr[0].val.programmaticStreamSerializationAllowed = 1;
        cfg.attrs = attr;
        cfg.numAttrs = 1;
        cfg.gridDim = dim3(nblk, 1, 1);
        cfg.blockDim = dim3(256, 1, 1);
        cfg.stream = 0;
        cudaLaunchKernelEx(&cfg, scatter_gt_kernel,
                           gt, out + grid_per_cloud, n, total_points);
    }
}